// round 2
// baseline (speedup 1.0000x reference)
#include <cuda_runtime.h>
#include <cuda_bf16.h>
#include <stdint.h>

// Problem constants (shapes fixed by the dataset)
#define MAX_NODES 50000
#define MAX_EDGES 800000
#define D_IN      128
#define D_E       64
#define NHEADS    4
#define D_OUTF    32
#define HD        128   // NHEADS * D_OUTF
#define NEG_SLOPE 0.2f
#define EPS_F     1e-16f

// ---------------- scratch (device globals; no allocation allowed) ----------
__device__ float g_HT[(size_t)MAX_NODES * HD];        // 25.6 MB
__device__ float g_alpha[(size_t)MAX_EDGES * NHEADS]; // 12.8 MB
__device__ int   g_deg[MAX_NODES];
__device__ int   g_off[MAX_NODES + 1];
__device__ int   g_cursor[MAX_NODES];
__device__ int   g_csr_src[MAX_EDGES];
__device__ int   g_csr_eid[MAX_EDGES];

// ---------------- packed f32x2 helpers (FFMA2) -----------------------------
__device__ __forceinline__ unsigned long long f2pack(float a, float b) {
    unsigned long long r;
    asm("mov.b64 %0, {%1, %2};" : "=l"(r) : "f"(a), "f"(b));
    return r;
}
__device__ __forceinline__ unsigned long long ffma2(unsigned long long a,
                                                    unsigned long long b,
                                                    unsigned long long c) {
    unsigned long long d;
    asm("fma.rn.f32x2 %0, %1, %2, %3;" : "=l"(d) : "l"(a), "l"(b), "l"(c));
    return d;
}
__device__ __forceinline__ float f2sum(unsigned long long a) {
    float lo, hi;
    asm("mov.b64 {%0, %1}, %2;" : "=f"(lo), "=f"(hi) : "l"(a));
    return lo + hi;
}

// ---------------- kernel: zero degree array ---------------------------------
__global__ void k_zero(int n_nodes) {
    int i = blockIdx.x * blockDim.x + threadIdx.x;
    if (i < n_nodes) g_deg[i] = 0;
}

// ---------------- kernel: HT = H @ W^T  (thread d owns output dim d) -------
__global__ __launch_bounds__(HD) void k_ht(const float* __restrict__ H,
                                           const float* __restrict__ W,
                                           int n_nodes) {
    int d = threadIdx.x;  // 0..127
    // W row d (128 floats) as 64 packed f32x2 in registers
    unsigned long long wreg[D_IN / 2];
    const unsigned long long* wrow =
        reinterpret_cast<const unsigned long long*>(W + (size_t)d * D_IN);
#pragma unroll
    for (int i = 0; i < D_IN / 2; i++) wreg[i] = wrow[i];

    __shared__ float4 hs[D_IN / 4];  // one node's H row
    for (int n = blockIdx.x; n < n_nodes; n += gridDim.x) {
        if (d < D_IN / 4)
            hs[d] = reinterpret_cast<const float4*>(H + (size_t)n * D_IN)[d];
        __syncthreads();
        unsigned long long acc = f2pack(0.f, 0.f);
#pragma unroll
        for (int i = 0; i < D_IN / 4; i++) {
            float4 h4 = hs[i];
            acc = ffma2(f2pack(h4.x, h4.y), wreg[2 * i + 0], acc);
            acc = ffma2(f2pack(h4.z, h4.w), wreg[2 * i + 1], acc);
        }
        g_HT[(size_t)n * HD + d] = f2sum(acc);
        __syncthreads();
    }
}

// ---------------- kernel: degree histogram ---------------------------------
__global__ void k_hist(const int* __restrict__ ei, int n_edges) {
    int i = blockIdx.x * blockDim.x + threadIdx.x;
    if (i < n_edges) atomicAdd(&g_deg[ei[n_edges + i]], 1);
}

// ---------------- kernel: single-block exclusive scan -> offsets -----------
__global__ void k_scan(int n_nodes) {
    __shared__ int s[1024];
    int tid = threadIdx.x;
    int chunk = (n_nodes + 1023) / 1024;
    int lo = min(tid * chunk, n_nodes);
    int hi = min(lo + chunk, n_nodes);
    int sum = 0;
    for (int i = lo; i < hi; i++) sum += g_deg[i];
    s[tid] = sum;
    __syncthreads();
    // Hillis-Steele inclusive scan
    for (int o = 1; o < 1024; o <<= 1) {
        int v = (tid >= o) ? s[tid - o] : 0;
        __syncthreads();
        s[tid] += v;
        __syncthreads();
    }
    int base = (tid > 0) ? s[tid - 1] : 0;
    for (int i = lo; i < hi; i++) {
        g_off[i] = base;
        g_cursor[i] = base;
        base += g_deg[i];
    }
    if (tid == 1023) g_off[n_nodes] = s[1023];
}

// ---------------- kernel: fill CSR ------------------------------------------
__global__ void k_fill(const int* __restrict__ ei, int n_edges) {
    int i = blockIdx.x * blockDim.x + threadIdx.x;
    if (i < n_edges) {
        int src = ei[i];
        int dst = ei[n_edges + i];
        int pos = atomicAdd(&g_cursor[dst], 1);
        g_csr_src[pos] = src;
        g_csr_eid[pos] = i;
    }
}

// ---------------- kernel: edge alpha logits ---------------------------------
// alpha[e,h] = sum_d att[h,d] * leakyrelu(HT[src,h,d] + HT[dst,h,d] + (E[e]@W_e^T)[h,d])
#define ETILE 16
__global__ __launch_bounds__(HD) void k_alpha(const float* __restrict__ E,
                                              const float* __restrict__ We,
                                              const int* __restrict__ ei,
                                              const float* __restrict__ att,
                                              int n_edges) {
    int d = threadIdx.x;        // output dim 0..127
    int w = d >> 5;             // warp == head
    int lane = d & 31;

    // W_e column for dim d: 64 floats = 32 packed f32x2 in registers
    unsigned long long wreg[D_E / 2];
    const unsigned long long* wrow =
        reinterpret_cast<const unsigned long long*>(We + (size_t)d * D_E);
#pragma unroll
    for (int i = 0; i < D_E / 2; i++) wreg[i] = wrow[i];
    float attd = att[d];

    __shared__ float4 es[ETILE * (D_E / 4)];  // 16 edges x 64 floats
    __shared__ int ssrc[ETILE], sdst[ETILE];

    int ntiles = (n_edges + ETILE - 1) / ETILE;
    for (int tile = blockIdx.x; tile < ntiles; tile += gridDim.x) {
        int e0 = tile * ETILE;
        int cnt = min(ETILE, n_edges - e0);
        // cooperative load: cnt*16 float4, coalesced
        for (int i = d; i < cnt * (D_E / 4); i += HD)
            es[i] = reinterpret_cast<const float4*>(E + (size_t)e0 * D_E)[i];
        if (d < cnt) ssrc[d] = ei[e0 + d];
        if (d >= 32 && d < 32 + cnt) sdst[d - 32] = ei[n_edges + e0 + (d - 32)];
        __syncthreads();

#pragma unroll 2
        for (int t = 0; t < cnt; t++) {
            int src = ssrc[t];
            int dst = sdst[t];
            float x = g_HT[(size_t)src * HD + d] + g_HT[(size_t)dst * HD + d];
            unsigned long long acc = f2pack(0.f, 0.f);
#pragma unroll
            for (int i = 0; i < D_E / 4; i++) {
                float4 ev = es[t * (D_E / 4) + i];
                acc = ffma2(f2pack(ev.x, ev.y), wreg[2 * i + 0], acc);
                acc = ffma2(f2pack(ev.z, ev.w), wreg[2 * i + 1], acc);
            }
            x += f2sum(acc);
            float y = (x > 0.f) ? x : NEG_SLOPE * x;
            float p = y * attd;
#pragma unroll
            for (int o = 16; o > 0; o >>= 1)
                p += __shfl_xor_sync(0xffffffffu, p, o);
            if (lane == 0) g_alpha[(size_t)(e0 + t) * NHEADS + w] = p;
        }
        __syncthreads();
    }
}

// ---------------- kernel: per-dst softmax + weighted aggregation -----------
#define AGG_CH 32
__global__ __launch_bounds__(HD) void k_agg(float* __restrict__ out, int n_nodes) {
    int n = blockIdx.x;
    int d = threadIdx.x;
    int w = d >> 5;
    int lane = d & 31;
    int start = g_off[n];
    int end = g_off[n + 1];
    int deg = end - start;

    if (deg == 0) {
        out[(size_t)n * HD + d] = 0.f;
        return;  // uniform across block: no divergent barrier
    }

    // phase 1: per-head (per-warp) max and sum of exp
    float m = -3.4e38f;
    for (int i = start + lane; i < end; i += 32)
        m = fmaxf(m, g_alpha[(size_t)g_csr_eid[i] * NHEADS + w]);
#pragma unroll
    for (int o = 16; o > 0; o >>= 1)
        m = fmaxf(m, __shfl_xor_sync(0xffffffffu, m, o));

    float s = 0.f;
    for (int i = start + lane; i < end; i += 32)
        s += __expf(g_alpha[(size_t)g_csr_eid[i] * NHEADS + w] - m);
#pragma unroll
    for (int o = 16; o > 0; o >>= 1)
        s += __shfl_xor_sync(0xffffffffu, s, o);
    float inv = 1.f / (s + EPS_F);

    // phase 2: chunked weighted aggregation (no atomics)
    __shared__ float cw[AGG_CH * NHEADS];
    __shared__ int cs[AGG_CH];
    float acc = 0.f;
    for (int cb = start; cb < end; cb += AGG_CH) {
        int c = min(AGG_CH, end - cb);
        for (int j = lane; j < c; j += 32) {
            int idx = cb + j;
            int eid = g_csr_eid[idx];
            cw[j * NHEADS + w] = __expf(g_alpha[(size_t)eid * NHEADS + w] - m) * inv;
            if (w == 0) cs[j] = g_csr_src[idx];
        }
        __syncthreads();
#pragma unroll 4
        for (int j = 0; j < c; j++)
            acc = fmaf(cw[j * NHEADS + w], g_HT[(size_t)cs[j] * HD + d], acc);
        __syncthreads();
    }
    out[(size_t)n * HD + d] = acc;
}

// ---------------- launcher ---------------------------------------------------
extern "C" void kernel_launch(void* const* d_in, const int* in_sizes, int n_in,
                              void* d_out, int out_size) {
    const float* H = (const float*)d_in[0];
    const int*   ei = (const int*)d_in[1];
    const float* E = (const float*)d_in[2];
    const float* W = (const float*)d_in[3];
    const float* We = (const float*)d_in[4];
    const float* att = (const float*)d_in[5];
    float* out = (float*)d_out;

    int n_nodes = in_sizes[0] / D_IN;
    int n_edges = in_sizes[1] / 2;

    k_zero<<<(n_nodes + 255) / 256, 256>>>(n_nodes);
    k_ht<<<1024, HD>>>(H, W, n_nodes);
    k_hist<<<(n_edges + 255) / 256, 256>>>(ei, n_edges);
    k_scan<<<1, 1024>>>(n_nodes);
    k_fill<<<(n_edges + 255) / 256, 256>>>(ei, n_edges);
    k_alpha<<<2048, HD>>>(E, We, ei, att, n_edges);
    k_agg<<<n_nodes, HD>>>(out, n_nodes);
}